// round 15
// baseline (speedup 1.0000x reference)
#include <cuda_runtime.h>
#include <cuda_fp16.h>
#include <stdint.h>
#include <string.h>
#include <math.h>

#define Bn 8
#define Cn 256
#define C2n 256
#define Hn 64
#define Wn 64
#define HWn 4096
#define KKn 9
#define Ktot 2304

// ---------------- device scratch (fp16) ----------------
__device__ float g_offset[Bn * 18 * HWn];
__device__ float g_mask[Bn * KKn * HWn];
__device__ __align__(16) __half g_whi[C2n * Ktot];   // dfconv weights (single fp16)
__device__ __align__(16) __half g_omhi[32 * Ktot];   // offset/mask weights (single fp16)
// x transposed to NHWC, single fp16: xt[b][y][w][c]
__device__ __align__(16) __half g_xhi[(size_t)Bn * HWn * Cn];

// ---------------- warp-level MMA helpers ----------------
__device__ __forceinline__ void ldsm4(uint32_t addr, uint32_t r[4]) {
    asm volatile("ldmatrix.sync.aligned.m8n8.x4.shared.b16 {%0,%1,%2,%3}, [%4];"
                 : "=r"(r[0]), "=r"(r[1]), "=r"(r[2]), "=r"(r[3]) : "r"(addr));
}
__device__ __forceinline__ void mma16816h(float d[4], const uint32_t a[4], const uint32_t b[2]) {
    asm volatile("mma.sync.aligned.m16n8k16.row.col.f32.f16.f16.f32 "
                 "{%0,%1,%2,%3}, {%4,%5,%6,%7}, {%8,%9}, {%0,%1,%2,%3};"
                 : "+f"(d[0]), "+f"(d[1]), "+f"(d[2]), "+f"(d[3])
                 : "r"(a[0]), "r"(a[1]), "r"(a[2]), "r"(a[3]), "r"(b[0]), "r"(b[1]));
}
__device__ __forceinline__ uint32_t smem_to_u32(const void* p) {
    uint32_t a;
    asm("{ .reg .u64 t; cvta.to.shared.u64 t, %1; cvt.u32.u64 %0, t; }" : "=r"(a) : "l"(p));
    return a;
}
__device__ __forceinline__ void cp_async16(uint32_t saddr, const void* gptr) {
    asm volatile("cp.async.cg.shared.global [%0], [%1], 16;" :: "r"(saddr), "l"(gptr));
}
// L1-caching variant: for tiles with heavy cross-iteration reuse (offmask A)
__device__ __forceinline__ void cp_async16_ca(uint32_t saddr, const void* gptr) {
    asm volatile("cp.async.ca.shared.global [%0], [%1], 16;" :: "r"(saddr), "l"(gptr));
}
#define CP_COMMIT()  asm volatile("cp.async.commit_group;" ::: "memory")
#define CP_WAIT0()   asm volatile("cp.async.wait_group 0;" ::: "memory")

__device__ __forceinline__ float2 hf2f(uint32_t u) {
    __half2 h = *reinterpret_cast<__half2*>(&u);
    return __half22float2(h);
}
// accumulate 8 channels: v[i] += w * x[i]   (single fp16 source)
__device__ __forceinline__ void accum8s(float v[8], uint4 h, float w) {
    float2 a;
    a = hf2f(h.x); v[0] = fmaf(w, a.x, v[0]); v[1] = fmaf(w, a.y, v[1]);
    a = hf2f(h.y); v[2] = fmaf(w, a.x, v[2]); v[3] = fmaf(w, a.y, v[3]);
    a = hf2f(h.z); v[4] = fmaf(w, a.x, v[4]); v[5] = fmaf(w, a.y, v[5]);
    a = hf2f(h.w); v[6] = fmaf(w, a.x, v[6]); v[7] = fmaf(w, a.y, v[7]);
}
__device__ __forceinline__ uint32_t pack_h2(float a, float b) {
    __half2 p = __floats2half2_rn(a, b);
    return *reinterpret_cast<uint32_t*>(&p);
}

// ----------------------------------------------------------------------------
// prep_all: blocks [0,512) transpose x -> NHWC fp16 (packed half2 stores);
// blocks [512,548) convert offset_w/mod_w -> g_omhi
// ----------------------------------------------------------------------------
__global__ __launch_bounds__(256) void prep_all_kernel(
    const float* __restrict__ x,
    const float* __restrict__ offset_w,
    const float* __restrict__ mod_w)
{
    const int t = threadIdx.x;
    if (blockIdx.x < 512) {
        extern __shared__ float tile[];   // 256 * 65 floats
        const int b = blockIdx.x >> 6;
        const int y = blockIdx.x & 63;
        const float* xs = x + (size_t)b * Cn * HWn + y * Wn;
        for (int i = t; i < 16384; i += 256) {
            int c = i >> 6;
            int w = i & 63;
            tile[c * 65 + w] = xs[(size_t)c * HWn + w];
        }
        __syncthreads();
        const size_t obase = ((size_t)(b * 64 + y) * 64) * 256;
        // packed stores: 2 consecutive channels -> one u32
        for (int i = t; i < 8192; i += 256) {
            int c2 = (i & 127) * 2;
            int w  = i >> 7;
            uint32_t p = pack_h2(tile[c2 * 65 + w], tile[(c2 + 1) * 65 + w]);
            *(uint32_t*)((char*)g_xhi + (obase + (size_t)w * 256 + c2) * 2) = p;
        }
    } else {
        for (int i = (blockIdx.x - 512) * 256 + t; i < 32 * Ktot; i += 36 * 256) {
            int j = i / Ktot;
            int k = i - j * Ktot;
            int tap = k >> 8;
            int c = k & 255;
            float v = 0.f;
            if (j < 18)      v = offset_w[((size_t)j * Cn + c) * 9 + tap];
            else if (j < 27) v = mod_w[((size_t)(j - 18) * Cn + c) * 9 + tap];
            g_omhi[i] = __float2half(v);
        }
    }
}

// ----------------------------------------------------------------------------
// Kernel A: blocks [0,256): offset + modulator conv as fp16 mma GEMM, single
// product, cp.async.ca double-buffered (L1-cached A restage). Blocks
// [256,348): convert reg_w -> g_whi.
// ----------------------------------------------------------------------------
#define OM_A0    0
#define OM_ASTR  16384
#define OM_B0    32768
#define OM_BSTR  4096
#define OM_SMEM  40960

__global__ __launch_bounds__(256, 3) void offmask_mma_kernel(
    const float* __restrict__ offset_b, const float* __restrict__ mod_b,
    const float* __restrict__ reg_w)
{
    const int t = threadIdx.x;

    if (blockIdx.x >= 256) {
        for (int i = (blockIdx.x - 256) * 256 + t; i < C2n * Ktot; i += 92 * 256) {
            int co = i / Ktot;
            int k = i - co * Ktot;
            int tap = k >> 8;
            int c = k & 255;
            g_whi[i] = __float2half(reg_w[((size_t)co * Cn + c) * 9 + tap]);
        }
        return;
    }

    extern __shared__ __align__(16) char osm[];
    const uint32_t osb = smem_to_u32(osm);

    const int tile = blockIdx.x;       // 256 tiles
    const int b    = tile >> 5;
    const int sb   = (tile & 31) * 128;

    const int wid  = t >> 5;
    const int lane = t & 31;
    const int wm   = wid & 3;
    const int wn   = wid >> 2;

    const uint32_t lxor = (uint32_t)((lane & 7) << 4);
    const uint32_t asel = (lane & 16) ? 16u : 0u;
    const uint32_t bsel = (lane & 8) ? 16u : 0u;
    const uint32_t aRowOff = (uint32_t)((wm * 32 + (lane & 15)) * 128);
    const uint32_t bRowOff = (uint32_t)(((wn * 16 + (lane & 7) + ((lane & 16) ? 8 : 0))) * 128);

    const int spx = t >> 1;
    const int ch  = (t & 1) * 32;
    const int ssp = sb + spx;
    const int sy  = ssp >> 6;
    const int sxw = ssp & 63;
    const uint32_t arow = (uint32_t)(spx * 128);
    const uint32_t pxor2 = (uint32_t)((spx & 7) << 4);
    const int bj  = t >> 3;
    const int bku = t & 7;
    const uint32_t bdst = (uint32_t)(bj * 128 + ((bku * 16) ^ ((bj & 7) << 4)));

    auto stageAB = [&](int kb, int buf) {
        const int tap = kb >> 2;
        const int c0  = (kb & 3) * 64;
        const int kbase = kb * 64;
        {
            uint32_t dst = osb + OM_B0 + (uint32_t)buf * OM_BSTR + bdst;
            cp_async16_ca(dst, g_omhi + (size_t)bj * Ktot + kbase + bku * 8);
        }
        {
            const int py  = sy + tap / 3 - 1;
            const int pxx = sxw + tap % 3 - 1;
            const uint32_t ab = osb + OM_A0 + (uint32_t)buf * OM_ASTR + arow;
            if (((unsigned)py < (unsigned)Hn) && ((unsigned)pxx < (unsigned)Wn)) {
                const size_t src = ((size_t)(b * 4096 + py * 64 + pxx)) * 256 + c0 + ch;
#pragma unroll
                for (int u = 0; u < 4; u++) {
                    uint32_t o = (uint32_t)((ch * 2 + u * 16) ^ pxor2);
                    cp_async16_ca(ab + o, g_xhi + src + u * 8);
                }
            } else {
                uint4 z = make_uint4(0, 0, 0, 0);
#pragma unroll
                for (int u = 0; u < 4; u++) {
                    uint32_t o = (uint32_t)((ch * 2 + u * 16) ^ pxor2);
                    *(uint4*)(osm + (ab - osb) + o) = z;
                }
            }
        }
    };

    float d[2][2][4];
#pragma unroll
    for (int mt = 0; mt < 2; mt++)
#pragma unroll
        for (int nt = 0; nt < 2; nt++)
#pragma unroll
            for (int j = 0; j < 4; j++) d[mt][nt][j] = 0.f;

    stageAB(0, 0);
    CP_COMMIT();
    CP_WAIT0();
    __syncthreads();

#pragma unroll 1
    for (int kb = 0; kb < 36; kb++) {
        if (kb < 35) {
            stageAB(kb + 1, (kb + 1) & 1);
            CP_COMMIT();
        }

        const uint32_t aA = osb + OM_A0 + (uint32_t)((kb & 1) * OM_ASTR) + aRowOff;
        const uint32_t bB = osb + OM_B0 + (uint32_t)((kb & 1) * OM_BSTR) + bRowOff;

#pragma unroll
        for (int ks = 0; ks < 4; ks++) {
            const uint32_t acol = (uint32_t)((ks * 32 + asel) ^ lxor);
            const uint32_t bcol = (uint32_t)((ks * 32 + bsel) ^ lxor);
            uint32_t Af[2][4], BH[4];
#pragma unroll
            for (int mt = 0; mt < 2; mt++)
                ldsm4(aA + mt * 2048 + acol, Af[mt]);
            ldsm4(bB + bcol, BH);
#pragma unroll
            for (int mt = 0; mt < 2; mt++)
#pragma unroll
                for (int nt = 0; nt < 2; nt++)
                    mma16816h(d[mt][nt], Af[mt], &BH[nt * 2]);
        }

        if (kb < 35) CP_WAIT0();
        __syncthreads();
    }

    // epilogue: clip/sigmoid, write g_offset / g_mask
    {
        const int g   = lane >> 2;
        const int tig = lane & 3;
#pragma unroll
        for (int mt = 0; mt < 2; mt++) {
#pragma unroll
            for (int nt = 0; nt < 2; nt++) {
#pragma unroll
                for (int r = 0; r < 4; r++) {
                    int px = wm * 32 + mt * 16 + g + ((r >= 2) ? 8 : 0);
                    int j  = wn * 16 + nt * 8 + tig * 2 + (r & 1);
                    int sp = sb + px;
                    float v = d[mt][nt][r];
                    if (j < 18) {
                        float o = fminf(16.f, fmaxf(-16.f, v + offset_b[j]));
                        g_offset[(size_t)(b * 18 + j) * HWn + sp] = o;
                    } else if (j < 27) {
                        float o = v + mod_b[j - 18];
                        g_mask[(size_t)(b * 9 + (j - 18)) * HWn + sp] = 1.f / (1.f + expf(-o));
                    }
                }
            }
        }
    }
}

// ----------------------------------------------------------------------------
// Kernel B: deformable conv GEMM, fp16 single product, single-plane x gather,
// smem double-buffered. M=128 x N=256, K-block 64. (unchanged R13/R14)
// ----------------------------------------------------------------------------
#define DF_TW     0        // float4[1152]  weights table     (18432 B)
#define DF_TIDX   18432    // ushort4[1152] corner idx table  ( 9216 B)
#define DF_A0     27648    // A buffers: 2 x 16384 (fp16 single)
#define DF_ASTR   16384
#define DF_B0     60416    // B buffers: 2 x 32768 (fp16 single)
#define DF_BSTR   32768
#define SMEM_BYTES 125952

__global__ __launch_bounds__(512, 1)
void dfconv_mma_kernel(float* __restrict__ out)
{
    extern __shared__ __align__(16) char smem[];
    const uint32_t smem_base = smem_to_u32(smem);
    const int t = threadIdx.x;

    const int tile = blockIdx.x;        // 256 tiles
    const int b    = tile >> 5;
    const int sb   = (tile & 31) * 128;

    // --- bilinear tables: 128 px x 9 taps ---
    float4*  tbl_w   = (float4*)(smem + DF_TW);
    ushort4* tbl_idx = (ushort4*)(smem + DF_TIDX);
    for (int e = t; e < 1152; e += 512) {
        int p   = e / 9;
        int tap = e - p * 9;
        int sp  = sb + p;
        int y   = sp >> 6;
        int xw  = sp & 63;
        float dy = g_offset[(size_t)(b * 18 + 2 * tap) * HWn + sp];
        float dx = g_offset[(size_t)(b * 18 + 2 * tap + 1) * HWn + sp];
        float m  = g_mask[(size_t)(b * 9 + tap) * HWn + sp];
        float py = dy + (float)(tap / 3) + (float)(y - 1);
        float px = dx + (float)(tap % 3) + (float)(xw - 1);
        float y0f = floorf(py), x0f = floorf(px);
        float ly = py - y0f, lx = px - x0f;
        int y0 = (int)y0f, x0 = (int)x0f;
        int y1 = y0 + 1, x1 = x0 + 1;
        float vy0 = ((unsigned)y0 < (unsigned)Hn) ? 1.f : 0.f;
        float vy1 = ((unsigned)y1 < (unsigned)Hn) ? 1.f : 0.f;
        float vx0 = ((unsigned)x0 < (unsigned)Wn) ? 1.f : 0.f;
        float vx1 = ((unsigned)x1 < (unsigned)Wn) ? 1.f : 0.f;
        float w00 = (1.f - ly) * (1.f - lx) * m * vy0 * vx0;
        float w01 = (1.f - ly) * lx        * m * vy0 * vx1;
        float w10 = ly        * (1.f - lx) * m * vy1 * vx0;
        float w11 = ly        * lx         * m * vy1 * vx1;
        int cy0 = min(max(y0, 0), Hn - 1), cy1 = min(max(y1, 0), Hn - 1);
        int cx0 = min(max(x0, 0), Wn - 1), cx1 = min(max(x1, 0), Wn - 1);
        tbl_w[e]   = make_float4(w00, w01, w10, w11);
        tbl_idx[e] = make_ushort4((unsigned short)(cy0 * Wn + cx0),
                                  (unsigned short)(cy0 * Wn + cx1),
                                  (unsigned short)(cy1 * Wn + cx0),
                                  (unsigned short)(cy1 * Wn + cx1));
    }
    __syncthreads();

    // gather role: px + 16-channel group
    const int gpx = t >> 2;
    const int cg  = t & 3;
    const uint32_t grow = (uint32_t)(gpx * 128);
    const uint32_t pxor = (uint32_t)((gpx & 7) << 4);

    // mma role
    const int wid  = t >> 5;
    const int lane = t & 31;
    const int wm   = wid & 1;
    const int wn   = wid >> 1;
    const uint32_t lxor = (uint32_t)((lane & 7) << 4);
    const uint32_t asel = (lane & 16) ? 16u : 0u;
    const uint32_t bsel = (lane & 8) ? 16u : 0u;
    const uint32_t aRow = (uint32_t)((wm * 64 + (lane & 15)) * 128);
    const uint32_t bRow = (uint32_t)((wn * 32 + (lane & 7) + ((lane & 16) ? 8 : 0)) * 128);
    const uint32_t aBase = smem_base + DF_A0 + aRow;
    const uint32_t bBase = smem_base + DF_B0 + bRow;

    auto stageB = [&](int kb, int buf) {
        const int kbase = kb * 64;
        const uint32_t bb = smem_base + DF_B0 + (uint32_t)buf * DF_BSTR;
#pragma unroll
        for (int it = 0; it < 4; it++) {
            int i  = t + it * 512;       // 0..2047
            int co = i >> 3;
            int k8 = i & 7;
            uint32_t so = (uint32_t)(co * 128 + ((k8 * 16) ^ ((co & 7) << 4)));
            cp_async16(bb + so, g_whi + (size_t)co * Ktot + kbase + k8 * 8);
        }
    };

    auto gatherA = [&](int kb, int buf) {
        const int tap = kb >> 2;
        const int c0  = (kb & 3) * 64;
        ushort4 id = tbl_idx[gpx * 9 + tap];
        float4  wt = tbl_w[gpx * 9 + tap];
        const size_t cbase = ((size_t)b * 4096) * 256 + c0 + cg * 16;
        const __half* p0 = g_xhi + cbase + (size_t)id.x * 256;
        const __half* p1 = g_xhi + cbase + (size_t)id.y * 256;
        const __half* p2 = g_xhi + cbase + (size_t)id.z * 256;
        const __half* p3 = g_xhi + cbase + (size_t)id.w * 256;
        const uint32_t ab = (uint32_t)(DF_A0 + buf * DF_ASTR) + grow;
#pragma unroll
        for (int u = 0; u < 2; u++) {
            float v[8];
#pragma unroll
            for (int i = 0; i < 8; i++) v[i] = 0.f;
            accum8s(v, ((const uint4*)p0)[u], wt.x);
            accum8s(v, ((const uint4*)p1)[u], wt.y);
            accum8s(v, ((const uint4*)p2)[u], wt.z);
            accum8s(v, ((const uint4*)p3)[u], wt.w);
            uint4 H;
            H.x = pack_h2(v[0], v[1]);
            H.y = pack_h2(v[2], v[3]);
            H.z = pack_h2(v[4], v[5]);
            H.w = pack_h2(v[6], v[7]);
            uint32_t o = (uint32_t)((cg * 32 + u * 16) ^ pxor);
            *(uint4*)(smem + ab + o) = H;
        }
    };

    float d[4][4][4];
#pragma unroll
    for (int mt = 0; mt < 4; mt++)
#pragma unroll
        for (int nt = 0; nt < 4; nt++)
#pragma unroll
            for (int j = 0; j < 4; j++) d[mt][nt][j] = 0.f;

    stageB(0, 0);
    CP_COMMIT();
    gatherA(0, 0);
    CP_WAIT0();
    __syncthreads();

#pragma unroll 1
    for (int kb = 0; kb < 36; kb++) {
        if (kb < 35) {
            stageB(kb + 1, (kb + 1) & 1);
            CP_COMMIT();
            gatherA(kb + 1, (kb + 1) & 1);
        }

        const uint32_t aA = aBase + (uint32_t)((kb & 1) * DF_ASTR);
        const uint32_t bH = bBase + (uint32_t)((kb & 1) * DF_BSTR);
#pragma unroll
        for (int ks = 0; ks < 4; ks++) {
            const uint32_t acol = (uint32_t)((ks * 32 + asel) ^ lxor);
            const uint32_t bcol = (uint32_t)((ks * 32 + bsel) ^ lxor);
            uint32_t Af[4][4], Bf[2][4];
#pragma unroll
            for (int mt = 0; mt < 4; mt++)
                ldsm4(aA + mt * 2048 + acol, Af[mt]);
            ldsm4(bH + bcol, Bf[0]);
            ldsm4(bH + 2048 + bcol, Bf[1]);
#pragma unroll
            for (int mt = 0; mt < 4; mt++)
#pragma unroll
                for (int nt = 0; nt < 4; nt++) {
                    const uint32_t* bp = &Bf[nt >> 1][(nt & 1) * 2];
                    mma16816h(d[mt][nt], Af[mt], bp);
                }
        }

        if (kb < 35) CP_WAIT0();
        __syncthreads();
    }

    // --- epilogue ---
    {
        const int g   = lane >> 2;
        const int tig = lane & 3;
        float* outb = out + (size_t)b * C2n * HWn + sb;
#pragma unroll
        for (int mt = 0; mt < 4; mt++) {
            const int px0 = wm * 64 + mt * 16 + g;
#pragma unroll
            for (int nt = 0; nt < 4; nt++) {
                const int co0 = wn * 32 + nt * 8 + tig * 2;
                outb[(size_t)co0 * HWn + px0]           = d[mt][nt][0];
                outb[(size_t)(co0 + 1) * HWn + px0]     = d[mt][nt][1];
                outb[(size_t)co0 * HWn + px0 + 8]       = d[mt][nt][2];
                outb[(size_t)(co0 + 1) * HWn + px0 + 8] = d[mt][nt][3];
            }
        }
    }
}

// ----------------------------------------------------------------------------
extern "C" void kernel_launch(void* const* d_in, const int* in_sizes, int n_in,
                              void* d_out, int out_size)
{
    const float* x        = (const float*)d_in[0];
    const float* offset_w = (const float*)d_in[1];
    const float* offset_b = (const float*)d_in[2];
    const float* mod_w    = (const float*)d_in[3];
    const float* mod_b    = (const float*)d_in[4];
    const float* reg_w    = (const float*)d_in[5];
    float* out = (float*)d_out;

    cudaFuncSetAttribute(dfconv_mma_kernel,
                         cudaFuncAttributeMaxDynamicSharedMemorySize, SMEM_BYTES);
    cudaFuncSetAttribute(offmask_mma_kernel,
                         cudaFuncAttributeMaxDynamicSharedMemorySize, OM_SMEM);
    cudaFuncSetAttribute(prep_all_kernel,
                         cudaFuncAttributeMaxDynamicSharedMemorySize, 256 * 65 * 4);

    prep_all_kernel<<<548, 256, 256 * 65 * 4>>>(x, offset_w, mod_w);
    offmask_mma_kernel<<<348, 256, OM_SMEM>>>(offset_b, mod_b, reg_w);
    dfconv_mma_kernel<<<256, 512, SMEM_BYTES>>>(out);
}

// round 16
// speedup vs baseline: 1.0791x; 1.0791x over previous
#include <cuda_runtime.h>
#include <cuda_fp16.h>
#include <stdint.h>
#include <string.h>
#include <math.h>

#define Bn 8
#define Cn 256
#define C2n 256
#define Hn 64
#define Wn 64
#define HWn 4096
#define KKn 9
#define Ktot 2304

// ---------------- device scratch (fp16) ----------------
__device__ float g_offset[Bn * 18 * HWn];
__device__ float g_mask[Bn * KKn * HWn];
__device__ __align__(16) __half g_whi[C2n * Ktot];   // dfconv weights (single fp16)
__device__ __align__(16) __half g_omhi[32 * Ktot];   // offset/mask weights (single fp16)
// x transposed to NHWC, single fp16: xt[b][y][w][c]
__device__ __align__(16) __half g_xhi[(size_t)Bn * HWn * Cn];

// ---------------- warp-level MMA helpers ----------------
__device__ __forceinline__ void ldsm4(uint32_t addr, uint32_t r[4]) {
    asm volatile("ldmatrix.sync.aligned.m8n8.x4.shared.b16 {%0,%1,%2,%3}, [%4];"
                 : "=r"(r[0]), "=r"(r[1]), "=r"(r[2]), "=r"(r[3]) : "r"(addr));
}
__device__ __forceinline__ void mma16816h(float d[4], const uint32_t a[4], const uint32_t b[2]) {
    asm volatile("mma.sync.aligned.m16n8k16.row.col.f32.f16.f16.f32 "
                 "{%0,%1,%2,%3}, {%4,%5,%6,%7}, {%8,%9}, {%0,%1,%2,%3};"
                 : "+f"(d[0]), "+f"(d[1]), "+f"(d[2]), "+f"(d[3])
                 : "r"(a[0]), "r"(a[1]), "r"(a[2]), "r"(a[3]), "r"(b[0]), "r"(b[1]));
}
__device__ __forceinline__ uint32_t smem_to_u32(const void* p) {
    uint32_t a;
    asm("{ .reg .u64 t; cvta.to.shared.u64 t, %1; cvt.u32.u64 %0, t; }" : "=r"(a) : "l"(p));
    return a;
}
__device__ __forceinline__ void cp_async16(uint32_t saddr, const void* gptr) {
    asm volatile("cp.async.cg.shared.global [%0], [%1], 16;" :: "r"(saddr), "l"(gptr));
}
#define CP_COMMIT()  asm volatile("cp.async.commit_group;" ::: "memory")
#define CP_WAIT0()   asm volatile("cp.async.wait_group 0;" ::: "memory")

__device__ __forceinline__ float2 hf2f(uint32_t u) {
    __half2 h = *reinterpret_cast<__half2*>(&u);
    return __half22float2(h);
}
// accumulate 8 channels: v[i] += w * x[i]   (single fp16 source)
__device__ __forceinline__ void accum8s(float v[8], uint4 h, float w) {
    float2 a;
    a = hf2f(h.x); v[0] = fmaf(w, a.x, v[0]); v[1] = fmaf(w, a.y, v[1]);
    a = hf2f(h.y); v[2] = fmaf(w, a.x, v[2]); v[3] = fmaf(w, a.y, v[3]);
    a = hf2f(h.z); v[4] = fmaf(w, a.x, v[4]); v[5] = fmaf(w, a.y, v[5]);
    a = hf2f(h.w); v[6] = fmaf(w, a.x, v[6]); v[7] = fmaf(w, a.y, v[7]);
}
__device__ __forceinline__ uint32_t pack_h2(float a, float b) {
    __half2 p = __floats2half2_rn(a, b);
    return *reinterpret_cast<uint32_t*>(&p);
}

// ----------------------------------------------------------------------------
// prep_all: blocks [0,1024) transpose x -> NHWC fp16 (one (b, y, c-half) per
// block; 33 KB tile -> ~6 CTAs/SM); blocks [1024,1060) convert offset_w/mod_w
// ----------------------------------------------------------------------------
__global__ __launch_bounds__(256) void prep_all_kernel(
    const float* __restrict__ x,
    const float* __restrict__ offset_w,
    const float* __restrict__ mod_w)
{
    const int t = threadIdx.x;
    if (blockIdx.x < 1024) {
        extern __shared__ float tile[];   // 128 * 65 floats = 33280 B
        const int b   = blockIdx.x >> 7;
        const int y   = (blockIdx.x >> 1) & 63;
        const int ch0 = (blockIdx.x & 1) * 128;
        const float* xs = x + (size_t)b * Cn * HWn + (size_t)ch0 * HWn + y * Wn;
        for (int i = t; i < 8192; i += 256) {
            int c = i >> 6;       // 0..127
            int w = i & 63;
            tile[c * 65 + w] = xs[(size_t)c * HWn + w];
        }
        __syncthreads();
        const size_t obase = ((size_t)(b * 64 + y) * 64) * 256 + ch0;
        for (int i = t; i < 4096; i += 256) {
            int c2 = (i & 63) * 2;    // 0..126
            int w  = i >> 6;
            uint32_t p = pack_h2(tile[c2 * 65 + w], tile[(c2 + 1) * 65 + w]);
            *(uint32_t*)((char*)g_xhi + (obase + (size_t)w * 256 + c2) * 2) = p;
        }
    } else {
        for (int i = (blockIdx.x - 1024) * 256 + t; i < 32 * Ktot; i += 36 * 256) {
            int j = i / Ktot;
            int k = i - j * Ktot;
            int tap = k >> 8;
            int c = k & 255;
            float v = 0.f;
            if (j < 18)      v = offset_w[((size_t)j * Cn + c) * 9 + tap];
            else if (j < 27) v = mod_w[((size_t)(j - 18) * Cn + c) * 9 + tap];
            g_omhi[i] = __float2half(v);
        }
    }
}

// ----------------------------------------------------------------------------
// Kernel A: blocks [0,256): offset + modulator conv as fp16 mma GEMM, single
// product, cp.async.cg double-buffered. Blocks [256,348): reg_w -> g_whi.
// ----------------------------------------------------------------------------
#define OM_A0    0
#define OM_ASTR  16384
#define OM_B0    32768
#define OM_BSTR  4096
#define OM_SMEM  40960

__global__ __launch_bounds__(256, 3) void offmask_mma_kernel(
    const float* __restrict__ offset_b, const float* __restrict__ mod_b,
    const float* __restrict__ reg_w)
{
    const int t = threadIdx.x;

    if (blockIdx.x >= 256) {
        for (int i = (blockIdx.x - 256) * 256 + t; i < C2n * Ktot; i += 92 * 256) {
            int co = i / Ktot;
            int k = i - co * Ktot;
            int tap = k >> 8;
            int c = k & 255;
            g_whi[i] = __float2half(reg_w[((size_t)co * Cn + c) * 9 + tap]);
        }
        return;
    }

    extern __shared__ __align__(16) char osm[];
    const uint32_t osb = smem_to_u32(osm);

    const int tile = blockIdx.x;       // 256 tiles
    const int b    = tile >> 5;
    const int sb   = (tile & 31) * 128;

    const int wid  = t >> 5;
    const int lane = t & 31;
    const int wm   = wid & 3;
    const int wn   = wid >> 2;

    const uint32_t lxor = (uint32_t)((lane & 7) << 4);
    const uint32_t asel = (lane & 16) ? 16u : 0u;
    const uint32_t bsel = (lane & 8) ? 16u : 0u;
    const uint32_t aRowOff = (uint32_t)((wm * 32 + (lane & 15)) * 128);
    const uint32_t bRowOff = (uint32_t)(((wn * 16 + (lane & 7) + ((lane & 16) ? 8 : 0))) * 128);

    const int spx = t >> 1;
    const int ch  = (t & 1) * 32;
    const int ssp = sb + spx;
    const int sy  = ssp >> 6;
    const int sxw = ssp & 63;
    const uint32_t arow = (uint32_t)(spx * 128);
    const uint32_t pxor2 = (uint32_t)((spx & 7) << 4);
    const int bj  = t >> 3;
    const int bku = t & 7;
    const uint32_t bdst = (uint32_t)(bj * 128 + ((bku * 16) ^ ((bj & 7) << 4)));

    auto stageAB = [&](int kb, int buf) {
        const int tap = kb >> 2;
        const int c0  = (kb & 3) * 64;
        const int kbase = kb * 64;
        {
            uint32_t dst = osb + OM_B0 + (uint32_t)buf * OM_BSTR + bdst;
            cp_async16(dst, g_omhi + (size_t)bj * Ktot + kbase + bku * 8);
        }
        {
            const int py  = sy + tap / 3 - 1;
            const int pxx = sxw + tap % 3 - 1;
            const uint32_t ab = osb + OM_A0 + (uint32_t)buf * OM_ASTR + arow;
            if (((unsigned)py < (unsigned)Hn) && ((unsigned)pxx < (unsigned)Wn)) {
                const size_t src = ((size_t)(b * 4096 + py * 64 + pxx)) * 256 + c0 + ch;
#pragma unroll
                for (int u = 0; u < 4; u++) {
                    uint32_t o = (uint32_t)((ch * 2 + u * 16) ^ pxor2);
                    cp_async16(ab + o, g_xhi + src + u * 8);
                }
            } else {
                uint4 z = make_uint4(0, 0, 0, 0);
#pragma unroll
                for (int u = 0; u < 4; u++) {
                    uint32_t o = (uint32_t)((ch * 2 + u * 16) ^ pxor2);
                    *(uint4*)(osm + (ab - osb) + o) = z;
                }
            }
        }
    };

    float d[2][2][4];
#pragma unroll
    for (int mt = 0; mt < 2; mt++)
#pragma unroll
        for (int nt = 0; nt < 2; nt++)
#pragma unroll
            for (int j = 0; j < 4; j++) d[mt][nt][j] = 0.f;

    stageAB(0, 0);
    CP_COMMIT();
    CP_WAIT0();
    __syncthreads();

#pragma unroll 1
    for (int kb = 0; kb < 36; kb++) {
        if (kb < 35) {
            stageAB(kb + 1, (kb + 1) & 1);
            CP_COMMIT();
        }

        const uint32_t aA = osb + OM_A0 + (uint32_t)((kb & 1) * OM_ASTR) + aRowOff;
        const uint32_t bB = osb + OM_B0 + (uint32_t)((kb & 1) * OM_BSTR) + bRowOff;

#pragma unroll
        for (int ks = 0; ks < 4; ks++) {
            const uint32_t acol = (uint32_t)((ks * 32 + asel) ^ lxor);
            const uint32_t bcol = (uint32_t)((ks * 32 + bsel) ^ lxor);
            uint32_t Af[2][4], BH[4];
#pragma unroll
            for (int mt = 0; mt < 2; mt++)
                ldsm4(aA + mt * 2048 + acol, Af[mt]);
            ldsm4(bB + bcol, BH);
#pragma unroll
            for (int mt = 0; mt < 2; mt++)
#pragma unroll
                for (int nt = 0; nt < 2; nt++)
                    mma16816h(d[mt][nt], Af[mt], &BH[nt * 2]);
        }

        if (kb < 35) CP_WAIT0();
        __syncthreads();
    }

    // epilogue: clip/sigmoid, write g_offset / g_mask
    {
        const int g   = lane >> 2;
        const int tig = lane & 3;
#pragma unroll
        for (int mt = 0; mt < 2; mt++) {
#pragma unroll
            for (int nt = 0; nt < 2; nt++) {
#pragma unroll
                for (int r = 0; r < 4; r++) {
                    int px = wm * 32 + mt * 16 + g + ((r >= 2) ? 8 : 0);
                    int j  = wn * 16 + nt * 8 + tig * 2 + (r & 1);
                    int sp = sb + px;
                    float v = d[mt][nt][r];
                    if (j < 18) {
                        float o = fminf(16.f, fmaxf(-16.f, v + offset_b[j]));
                        g_offset[(size_t)(b * 18 + j) * HWn + sp] = o;
                    } else if (j < 27) {
                        float o = v + mod_b[j - 18];
                        g_mask[(size_t)(b * 9 + (j - 18)) * HWn + sp] = 1.f / (1.f + expf(-o));
                    }
                }
            }
        }
    }
}

// ----------------------------------------------------------------------------
// Kernel B: deformable conv GEMM, fp16 single product, single-plane x gather,
// smem double-buffered. M=128 x N=256, K-block 64. (unchanged R13/R14)
// ----------------------------------------------------------------------------
#define DF_TW     0        // float4[1152]  weights table     (18432 B)
#define DF_TIDX   18432    // ushort4[1152] corner idx table  ( 9216 B)
#define DF_A0     27648    // A buffers: 2 x 16384 (fp16 single)
#define DF_ASTR   16384
#define DF_B0     60416    // B buffers: 2 x 32768 (fp16 single)
#define DF_BSTR   32768
#define SMEM_BYTES 125952

__global__ __launch_bounds__(512, 1)
void dfconv_mma_kernel(float* __restrict__ out)
{
    extern __shared__ __align__(16) char smem[];
    const uint32_t smem_base = smem_to_u32(smem);
    const int t = threadIdx.x;

    const int tile = blockIdx.x;        // 256 tiles
    const int b    = tile >> 5;
    const int sb   = (tile & 31) * 128;

    // --- bilinear tables: 128 px x 9 taps ---
    float4*  tbl_w   = (float4*)(smem + DF_TW);
    ushort4* tbl_idx = (ushort4*)(smem + DF_TIDX);
    for (int e = t; e < 1152; e += 512) {
        int p   = e / 9;
        int tap = e - p * 9;
        int sp  = sb + p;
        int y   = sp >> 6;
        int xw  = sp & 63;
        float dy = g_offset[(size_t)(b * 18 + 2 * tap) * HWn + sp];
        float dx = g_offset[(size_t)(b * 18 + 2 * tap + 1) * HWn + sp];
        float m  = g_mask[(size_t)(b * 9 + tap) * HWn + sp];
        float py = dy + (float)(tap / 3) + (float)(y - 1);
        float px = dx + (float)(tap % 3) + (float)(xw - 1);
        float y0f = floorf(py), x0f = floorf(px);
        float ly = py - y0f, lx = px - x0f;
        int y0 = (int)y0f, x0 = (int)x0f;
        int y1 = y0 + 1, x1 = x0 + 1;
        float vy0 = ((unsigned)y0 < (unsigned)Hn) ? 1.f : 0.f;
        float vy1 = ((unsigned)y1 < (unsigned)Hn) ? 1.f : 0.f;
        float vx0 = ((unsigned)x0 < (unsigned)Wn) ? 1.f : 0.f;
        float vx1 = ((unsigned)x1 < (unsigned)Wn) ? 1.f : 0.f;
        float w00 = (1.f - ly) * (1.f - lx) * m * vy0 * vx0;
        float w01 = (1.f - ly) * lx        * m * vy0 * vx1;
        float w10 = ly        * (1.f - lx) * m * vy1 * vx0;
        float w11 = ly        * lx         * m * vy1 * vx1;
        int cy0 = min(max(y0, 0), Hn - 1), cy1 = min(max(y1, 0), Hn - 1);
        int cx0 = min(max(x0, 0), Wn - 1), cx1 = min(max(x1, 0), Wn - 1);
        tbl_w[e]   = make_float4(w00, w01, w10, w11);
        tbl_idx[e] = make_ushort4((unsigned short)(cy0 * Wn + cx0),
                                  (unsigned short)(cy0 * Wn + cx1),
                                  (unsigned short)(cy1 * Wn + cx0),
                                  (unsigned short)(cy1 * Wn + cx1));
    }
    __syncthreads();

    // gather role: px + 16-channel group
    const int gpx = t >> 2;
    const int cg  = t & 3;
    const uint32_t grow = (uint32_t)(gpx * 128);
    const uint32_t pxor = (uint32_t)((gpx & 7) << 4);

    // mma role
    const int wid  = t >> 5;
    const int lane = t & 31;
    const int wm   = wid & 1;
    const int wn   = wid >> 1;
    const uint32_t lxor = (uint32_t)((lane & 7) << 4);
    const uint32_t asel = (lane & 16) ? 16u : 0u;
    const uint32_t bsel = (lane & 8) ? 16u : 0u;
    const uint32_t aRow = (uint32_t)((wm * 64 + (lane & 15)) * 128);
    const uint32_t bRow = (uint32_t)((wn * 32 + (lane & 7) + ((lane & 16) ? 8 : 0)) * 128);
    const uint32_t aBase = smem_base + DF_A0 + aRow;
    const uint32_t bBase = smem_base + DF_B0 + bRow;

    auto stageB = [&](int kb, int buf) {
        const int kbase = kb * 64;
        const uint32_t bb = smem_base + DF_B0 + (uint32_t)buf * DF_BSTR;
#pragma unroll
        for (int it = 0; it < 4; it++) {
            int i  = t + it * 512;       // 0..2047
            int co = i >> 3;
            int k8 = i & 7;
            uint32_t so = (uint32_t)(co * 128 + ((k8 * 16) ^ ((co & 7) << 4)));
            cp_async16(bb + so, g_whi + (size_t)co * Ktot + kbase + k8 * 8);
        }
    };

    auto gatherA = [&](int kb, int buf) {
        const int tap = kb >> 2;
        const int c0  = (kb & 3) * 64;
        ushort4 id = tbl_idx[gpx * 9 + tap];
        float4  wt = tbl_w[gpx * 9 + tap];
        const size_t cbase = ((size_t)b * 4096) * 256 + c0 + cg * 16;
        const __half* p0 = g_xhi + cbase + (size_t)id.x * 256;
        const __half* p1 = g_xhi + cbase + (size_t)id.y * 256;
        const __half* p2 = g_xhi + cbase + (size_t)id.z * 256;
        const __half* p3 = g_xhi + cbase + (size_t)id.w * 256;
        const uint32_t ab = (uint32_t)(DF_A0 + buf * DF_ASTR) + grow;
#pragma unroll
        for (int u = 0; u < 2; u++) {
            float v[8];
#pragma unroll
            for (int i = 0; i < 8; i++) v[i] = 0.f;
            accum8s(v, ((const uint4*)p0)[u], wt.x);
            accum8s(v, ((const uint4*)p1)[u], wt.y);
            accum8s(v, ((const uint4*)p2)[u], wt.z);
            accum8s(v, ((const uint4*)p3)[u], wt.w);
            uint4 H;
            H.x = pack_h2(v[0], v[1]);
            H.y = pack_h2(v[2], v[3]);
            H.z = pack_h2(v[4], v[5]);
            H.w = pack_h2(v[6], v[7]);
            uint32_t o = (uint32_t)((cg * 32 + u * 16) ^ pxor);
            *(uint4*)(smem + ab + o) = H;
        }
    };

    float d[4][4][4];
#pragma unroll
    for (int mt = 0; mt < 4; mt++)
#pragma unroll
        for (int nt = 0; nt < 4; nt++)
#pragma unroll
            for (int j = 0; j < 4; j++) d[mt][nt][j] = 0.f;

    stageB(0, 0);
    CP_COMMIT();
    gatherA(0, 0);
    CP_WAIT0();
    __syncthreads();

#pragma unroll 1
    for (int kb = 0; kb < 36; kb++) {
        if (kb < 35) {
            stageB(kb + 1, (kb + 1) & 1);
            CP_COMMIT();
            gatherA(kb + 1, (kb + 1) & 1);
        }

        const uint32_t aA = aBase + (uint32_t)((kb & 1) * DF_ASTR);
        const uint32_t bH = bBase + (uint32_t)((kb & 1) * DF_BSTR);
#pragma unroll
        for (int ks = 0; ks < 4; ks++) {
            const uint32_t acol = (uint32_t)((ks * 32 + asel) ^ lxor);
            const uint32_t bcol = (uint32_t)((ks * 32 + bsel) ^ lxor);
            uint32_t Af[4][4], Bf[2][4];
#pragma unroll
            for (int mt = 0; mt < 4; mt++)
                ldsm4(aA + mt * 2048 + acol, Af[mt]);
            ldsm4(bH + bcol, Bf[0]);
            ldsm4(bH + 2048 + bcol, Bf[1]);
#pragma unroll
            for (int mt = 0; mt < 4; mt++)
#pragma unroll
                for (int nt = 0; nt < 4; nt++) {
                    const uint32_t* bp = &Bf[nt >> 1][(nt & 1) * 2];
                    mma16816h(d[mt][nt], Af[mt], bp);
                }
        }

        if (kb < 35) CP_WAIT0();
        __syncthreads();
    }

    // --- epilogue ---
    {
        const int g   = lane >> 2;
        const int tig = lane & 3;
        float* outb = out + (size_t)b * C2n * HWn + sb;
#pragma unroll
        for (int mt = 0; mt < 4; mt++) {
            const int px0 = wm * 64 + mt * 16 + g;
#pragma unroll
            for (int nt = 0; nt < 4; nt++) {
                const int co0 = wn * 32 + nt * 8 + tig * 2;
                outb[(size_t)co0 * HWn + px0]           = d[mt][nt][0];
                outb[(size_t)(co0 + 1) * HWn + px0]     = d[mt][nt][1];
                outb[(size_t)co0 * HWn + px0 + 8]       = d[mt][nt][2];
                outb[(size_t)(co0 + 1) * HWn + px0 + 8] = d[mt][nt][3];
            }
        }
    }
}

// ----------------------------------------------------------------------------
extern "C" void kernel_launch(void* const* d_in, const int* in_sizes, int n_in,
                              void* d_out, int out_size)
{
    const float* x        = (const float*)d_in[0];
    const float* offset_w = (const float*)d_in[1];
    const float* offset_b = (const float*)d_in[2];
    const float* mod_w    = (const float*)d_in[3];
    const float* mod_b    = (const float*)d_in[4];
    const float* reg_w    = (const float*)d_in[5];
    float* out = (float*)d_out;

    cudaFuncSetAttribute(dfconv_mma_kernel,
                         cudaFuncAttributeMaxDynamicSharedMemorySize, SMEM_BYTES);
    cudaFuncSetAttribute(offmask_mma_kernel,
                         cudaFuncAttributeMaxDynamicSharedMemorySize, OM_SMEM);
    cudaFuncSetAttribute(prep_all_kernel,
                         cudaFuncAttributeMaxDynamicSharedMemorySize, 128 * 65 * 4);

    prep_all_kernel<<<1060, 256, 128 * 65 * 4>>>(x, offset_w, mod_w);
    offmask_mma_kernel<<<348, 256, OM_SMEM>>>(offset_b, mod_b, reg_w);
    dfconv_mma_kernel<<<256, 512, SMEM_BYTES>>>(out);
}

// round 17
// speedup vs baseline: 1.0888x; 1.0089x over previous
#include <cuda_runtime.h>
#include <cuda_fp16.h>
#include <stdint.h>
#include <string.h>
#include <math.h>

#define Bn 8
#define Cn 256
#define C2n 256
#define Hn 64
#define Wn 64
#define HWn 4096
#define KKn 9
#define Ktot 2304

// ---------------- device scratch (fp16) ----------------
__device__ float g_offset[Bn * 18 * HWn];
__device__ float g_mask[Bn * KKn * HWn];
__device__ __align__(16) __half g_whi[C2n * Ktot];   // dfconv weights (single fp16)
__device__ __align__(16) __half g_omhi[32 * Ktot];   // offset/mask weights (single fp16)
// x transposed to NHWC, single fp16: xt[b][y][w][c]
__device__ __align__(16) __half g_xhi[(size_t)Bn * HWn * Cn];

// ---------------- warp-level MMA helpers ----------------
__device__ __forceinline__ void ldsm4(uint32_t addr, uint32_t r[4]) {
    asm volatile("ldmatrix.sync.aligned.m8n8.x4.shared.b16 {%0,%1,%2,%3}, [%4];"
                 : "=r"(r[0]), "=r"(r[1]), "=r"(r[2]), "=r"(r[3]) : "r"(addr));
}
__device__ __forceinline__ void mma16816h(float d[4], const uint32_t a[4], const uint32_t b[2]) {
    asm volatile("mma.sync.aligned.m16n8k16.row.col.f32.f16.f16.f32 "
                 "{%0,%1,%2,%3}, {%4,%5,%6,%7}, {%8,%9}, {%0,%1,%2,%3};"
                 : "+f"(d[0]), "+f"(d[1]), "+f"(d[2]), "+f"(d[3])
                 : "r"(a[0]), "r"(a[1]), "r"(a[2]), "r"(a[3]), "r"(b[0]), "r"(b[1]));
}
__device__ __forceinline__ uint32_t smem_to_u32(const void* p) {
    uint32_t a;
    asm("{ .reg .u64 t; cvta.to.shared.u64 t, %1; cvt.u32.u64 %0, t; }" : "=r"(a) : "l"(p));
    return a;
}
__device__ __forceinline__ void cp_async16(uint32_t saddr, const void* gptr) {
    asm volatile("cp.async.cg.shared.global [%0], [%1], 16;" :: "r"(saddr), "l"(gptr));
}
#define CP_COMMIT()  asm volatile("cp.async.commit_group;" ::: "memory")
#define CP_WAIT0()   asm volatile("cp.async.wait_group 0;" ::: "memory")
#define CP_WAIT1()   asm volatile("cp.async.wait_group 1;" ::: "memory")

__device__ __forceinline__ float2 hf2f(uint32_t u) {
    __half2 h = *reinterpret_cast<__half2*>(&u);
    return __half22float2(h);
}
// accumulate 8 channels: v[i] += w * x[i]   (single fp16 source)
__device__ __forceinline__ void accum8s(float v[8], uint4 h, float w) {
    float2 a;
    a = hf2f(h.x); v[0] = fmaf(w, a.x, v[0]); v[1] = fmaf(w, a.y, v[1]);
    a = hf2f(h.y); v[2] = fmaf(w, a.x, v[2]); v[3] = fmaf(w, a.y, v[3]);
    a = hf2f(h.z); v[4] = fmaf(w, a.x, v[4]); v[5] = fmaf(w, a.y, v[5]);
    a = hf2f(h.w); v[6] = fmaf(w, a.x, v[6]); v[7] = fmaf(w, a.y, v[7]);
}
__device__ __forceinline__ uint32_t pack_h2(float a, float b) {
    __half2 p = __floats2half2_rn(a, b);
    return *reinterpret_cast<uint32_t*>(&p);
}

// ----------------------------------------------------------------------------
// prep_all: blocks [0,1024) transpose x -> NHWC fp16 (one (b, y, c-half) per
// block); blocks [1024,1060) convert offset_w/mod_w
// ----------------------------------------------------------------------------
__global__ __launch_bounds__(256) void prep_all_kernel(
    const float* __restrict__ x,
    const float* __restrict__ offset_w,
    const float* __restrict__ mod_w)
{
    const int t = threadIdx.x;
    if (blockIdx.x < 1024) {
        extern __shared__ float tile[];   // 128 * 65 floats = 33280 B
        const int b   = blockIdx.x >> 7;
        const int y   = (blockIdx.x >> 1) & 63;
        const int ch0 = (blockIdx.x & 1) * 128;
        const float* xs = x + (size_t)b * Cn * HWn + (size_t)ch0 * HWn + y * Wn;
        for (int i = t; i < 8192; i += 256) {
            int c = i >> 6;
            int w = i & 63;
            tile[c * 65 + w] = xs[(size_t)c * HWn + w];
        }
        __syncthreads();
        const size_t obase = ((size_t)(b * 64 + y) * 64) * 256 + ch0;
        for (int i = t; i < 4096; i += 256) {
            int c2 = (i & 63) * 2;
            int w  = i >> 6;
            uint32_t p = pack_h2(tile[c2 * 65 + w], tile[(c2 + 1) * 65 + w]);
            *(uint32_t*)((char*)g_xhi + (obase + (size_t)w * 256 + c2) * 2) = p;
        }
    } else {
        for (int i = (blockIdx.x - 1024) * 256 + t; i < 32 * Ktot; i += 36 * 256) {
            int j = i / Ktot;
            int k = i - j * Ktot;
            int tap = k >> 8;
            int c = k & 255;
            float v = 0.f;
            if (j < 18)      v = offset_w[((size_t)j * Cn + c) * 9 + tap];
            else if (j < 27) v = mod_w[((size_t)(j - 18) * Cn + c) * 9 + tap];
            g_omhi[i] = __float2half(v);
        }
    }
}

// ----------------------------------------------------------------------------
// Kernel A: blocks [0,256): offset + modulator conv as fp16 mma GEMM, single
// product, cp.async TRIPLE-buffered (wait_group 1 keeps newest stage in
// flight). Blocks [256,348): reg_w -> g_whi.
// smem: A 3x16K + B 3x4K = 61440 B; occ 3.
// ----------------------------------------------------------------------------
#define OM_A0    0
#define OM_ASTR  16384
#define OM_B0    49152
#define OM_BSTR  4096
#define OM_SMEM  61440

__global__ __launch_bounds__(256, 3) void offmask_mma_kernel(
    const float* __restrict__ offset_b, const float* __restrict__ mod_b,
    const float* __restrict__ reg_w)
{
    const int t = threadIdx.x;

    if (blockIdx.x >= 256) {
        for (int i = (blockIdx.x - 256) * 256 + t; i < C2n * Ktot; i += 92 * 256) {
            int co = i / Ktot;
            int k = i - co * Ktot;
            int tap = k >> 8;
            int c = k & 255;
            g_whi[i] = __float2half(reg_w[((size_t)co * Cn + c) * 9 + tap]);
        }
        return;
    }

    extern __shared__ __align__(16) char osm[];
    const uint32_t osb = smem_to_u32(osm);

    const int tile = blockIdx.x;       // 256 tiles
    const int b    = tile >> 5;
    const int sb   = (tile & 31) * 128;

    const int wid  = t >> 5;
    const int lane = t & 31;
    const int wm   = wid & 3;
    const int wn   = wid >> 2;

    const uint32_t lxor = (uint32_t)((lane & 7) << 4);
    const uint32_t asel = (lane & 16) ? 16u : 0u;
    const uint32_t bsel = (lane & 8) ? 16u : 0u;
    const uint32_t aRowOff = (uint32_t)((wm * 32 + (lane & 15)) * 128);
    const uint32_t bRowOff = (uint32_t)(((wn * 16 + (lane & 7) + ((lane & 16) ? 8 : 0))) * 128);

    const int spx = t >> 1;
    const int ch  = (t & 1) * 32;
    const int ssp = sb + spx;
    const int sy  = ssp >> 6;
    const int sxw = ssp & 63;
    const uint32_t arow = (uint32_t)(spx * 128);
    const uint32_t pxor2 = (uint32_t)((spx & 7) << 4);
    const int bj  = t >> 3;
    const int bku = t & 7;
    const uint32_t bdst = (uint32_t)(bj * 128 + ((bku * 16) ^ ((bj & 7) << 4)));

    auto stageAB = [&](int kb, int buf) {
        const int tap = kb >> 2;
        const int c0  = (kb & 3) * 64;
        const int kbase = kb * 64;
        {
            uint32_t dst = osb + OM_B0 + (uint32_t)buf * OM_BSTR + bdst;
            cp_async16(dst, g_omhi + (size_t)bj * Ktot + kbase + bku * 8);
        }
        {
            const int py  = sy + tap / 3 - 1;
            const int pxx = sxw + tap % 3 - 1;
            const uint32_t ab = osb + OM_A0 + (uint32_t)buf * OM_ASTR + arow;
            if (((unsigned)py < (unsigned)Hn) && ((unsigned)pxx < (unsigned)Wn)) {
                const size_t src = ((size_t)(b * 4096 + py * 64 + pxx)) * 256 + c0 + ch;
#pragma unroll
                for (int u = 0; u < 4; u++) {
                    uint32_t o = (uint32_t)((ch * 2 + u * 16) ^ pxor2);
                    cp_async16(ab + o, g_xhi + src + u * 8);
                }
            } else {
                uint4 z = make_uint4(0, 0, 0, 0);
#pragma unroll
                for (int u = 0; u < 4; u++) {
                    uint32_t o = (uint32_t)((ch * 2 + u * 16) ^ pxor2);
                    *(uint4*)(osm + (ab - osb) + o) = z;
                }
            }
        }
    };

    float d[2][2][4];
#pragma unroll
    for (int mt = 0; mt < 2; mt++)
#pragma unroll
        for (int nt = 0; nt < 2; nt++)
#pragma unroll
            for (int j = 0; j < 4; j++) d[mt][nt][j] = 0.f;

    // prologue: buffers 0 and 1 in flight; ensure 0 complete
    stageAB(0, 0);
    CP_COMMIT();
    stageAB(1, 1);
    CP_COMMIT();
    CP_WAIT1();
    __syncthreads();

    int cur = 0;   // buffer holding kb
    int nxt = 2;   // buffer to fill with kb+2
#pragma unroll 1
    for (int kb = 0; kb < 36; kb++) {
        if (kb + 2 < 36) {
            stageAB(kb + 2, nxt);
            CP_COMMIT();
        }

        const uint32_t aA = osb + OM_A0 + (uint32_t)cur * OM_ASTR + aRowOff;
        const uint32_t bB = osb + OM_B0 + (uint32_t)cur * OM_BSTR + bRowOff;

#pragma unroll
        for (int ks = 0; ks < 4; ks++) {
            const uint32_t acol = (uint32_t)((ks * 32 + asel) ^ lxor);
            const uint32_t bcol = (uint32_t)((ks * 32 + bsel) ^ lxor);
            uint32_t Af[2][4], BH[4];
#pragma unroll
            for (int mt = 0; mt < 2; mt++)
                ldsm4(aA + mt * 2048 + acol, Af[mt]);
            ldsm4(bB + bcol, BH);
#pragma unroll
            for (int mt = 0; mt < 2; mt++)
#pragma unroll
                for (int nt = 0; nt < 2; nt++)
                    mma16816h(d[mt][nt], Af[mt], &BH[nt * 2]);
        }

        // ensure kb+1's buffer is complete before next iteration's mma;
        // keep the newest stage (kb+2) in flight when it exists
        if (kb + 2 < 36) CP_WAIT1(); else CP_WAIT0();
        __syncthreads();

        cur = (cur == 2) ? 0 : cur + 1;
        nxt = (nxt == 2) ? 0 : nxt + 1;
    }

    // epilogue: clip/sigmoid, write g_offset / g_mask
    {
        const int g   = lane >> 2;
        const int tig = lane & 3;
#pragma unroll
        for (int mt = 0; mt < 2; mt++) {
#pragma unroll
            for (int nt = 0; nt < 2; nt++) {
#pragma unroll
                for (int r = 0; r < 4; r++) {
                    int px = wm * 32 + mt * 16 + g + ((r >= 2) ? 8 : 0);
                    int j  = wn * 16 + nt * 8 + tig * 2 + (r & 1);
                    int sp = sb + px;
                    float v = d[mt][nt][r];
                    if (j < 18) {
                        float o = fminf(16.f, fmaxf(-16.f, v + offset_b[j]));
                        g_offset[(size_t)(b * 18 + j) * HWn + sp] = o;
                    } else if (j < 27) {
                        float o = v + mod_b[j - 18];
                        g_mask[(size_t)(b * 9 + (j - 18)) * HWn + sp] = 1.f / (1.f + expf(-o));
                    }
                }
            }
        }
    }
}

// ----------------------------------------------------------------------------
// Kernel B: deformable conv GEMM, fp16 single product, single-plane x gather,
// smem double-buffered. M=128 x N=256, K-block 64. (unchanged R13-R16)
// ----------------------------------------------------------------------------
#define DF_TW     0        // float4[1152]  weights table     (18432 B)
#define DF_TIDX   18432    // ushort4[1152] corner idx table  ( 9216 B)
#define DF_A0     27648    // A buffers: 2 x 16384 (fp16 single)
#define DF_ASTR   16384
#define DF_B0     60416    // B buffers: 2 x 32768 (fp16 single)
#define DF_BSTR   32768
#define SMEM_BYTES 125952

__global__ __launch_bounds__(512, 1)
void dfconv_mma_kernel(float* __restrict__ out)
{
    extern __shared__ __align__(16) char smem[];
    const uint32_t smem_base = smem_to_u32(smem);
    const int t = threadIdx.x;

    const int tile = blockIdx.x;        // 256 tiles
    const int b    = tile >> 5;
    const int sb   = (tile & 31) * 128;

    // --- bilinear tables: 128 px x 9 taps ---
    float4*  tbl_w   = (float4*)(smem + DF_TW);
    ushort4* tbl_idx = (ushort4*)(smem + DF_TIDX);
    for (int e = t; e < 1152; e += 512) {
        int p   = e / 9;
        int tap = e - p * 9;
        int sp  = sb + p;
        int y   = sp >> 6;
        int xw  = sp & 63;
        float dy = g_offset[(size_t)(b * 18 + 2 * tap) * HWn + sp];
        float dx = g_offset[(size_t)(b * 18 + 2 * tap + 1) * HWn + sp];
        float m  = g_mask[(size_t)(b * 9 + tap) * HWn + sp];
        float py = dy + (float)(tap / 3) + (float)(y - 1);
        float px = dx + (float)(tap % 3) + (float)(xw - 1);
        float y0f = floorf(py), x0f = floorf(px);
        float ly = py - y0f, lx = px - x0f;
        int y0 = (int)y0f, x0 = (int)x0f;
        int y1 = y0 + 1, x1 = x0 + 1;
        float vy0 = ((unsigned)y0 < (unsigned)Hn) ? 1.f : 0.f;
        float vy1 = ((unsigned)y1 < (unsigned)Hn) ? 1.f : 0.f;
        float vx0 = ((unsigned)x0 < (unsigned)Wn) ? 1.f : 0.f;
        float vx1 = ((unsigned)x1 < (unsigned)Wn) ? 1.f : 0.f;
        float w00 = (1.f - ly) * (1.f - lx) * m * vy0 * vx0;
        float w01 = (1.f - ly) * lx        * m * vy0 * vx1;
        float w10 = ly        * (1.f - lx) * m * vy1 * vx0;
        float w11 = ly        * lx         * m * vy1 * vx1;
        int cy0 = min(max(y0, 0), Hn - 1), cy1 = min(max(y1, 0), Hn - 1);
        int cx0 = min(max(x0, 0), Wn - 1), cx1 = min(max(x1, 0), Wn - 1);
        tbl_w[e]   = make_float4(w00, w01, w10, w11);
        tbl_idx[e] = make_ushort4((unsigned short)(cy0 * Wn + cx0),
                                  (unsigned short)(cy0 * Wn + cx1),
                                  (unsigned short)(cy1 * Wn + cx0),
                                  (unsigned short)(cy1 * Wn + cx1));
    }
    __syncthreads();

    // gather role: px + 16-channel group
    const int gpx = t >> 2;
    const int cg  = t & 3;
    const uint32_t grow = (uint32_t)(gpx * 128);
    const uint32_t pxor = (uint32_t)((gpx & 7) << 4);

    // mma role
    const int wid  = t >> 5;
    const int lane = t & 31;
    const int wm   = wid & 1;
    const int wn   = wid >> 1;
    const uint32_t lxor = (uint32_t)((lane & 7) << 4);
    const uint32_t asel = (lane & 16) ? 16u : 0u;
    const uint32_t bsel = (lane & 8) ? 16u : 0u;
    const uint32_t aRow = (uint32_t)((wm * 64 + (lane & 15)) * 128);
    const uint32_t bRow = (uint32_t)((wn * 32 + (lane & 7) + ((lane & 16) ? 8 : 0)) * 128);
    const uint32_t aBase = smem_base + DF_A0 + aRow;
    const uint32_t bBase = smem_base + DF_B0 + bRow;

    auto stageB = [&](int kb, int buf) {
        const int kbase = kb * 64;
        const uint32_t bb = smem_base + DF_B0 + (uint32_t)buf * DF_BSTR;
#pragma unroll
        for (int it = 0; it < 4; it++) {
            int i  = t + it * 512;       // 0..2047
            int co = i >> 3;
            int k8 = i & 7;
            uint32_t so = (uint32_t)(co * 128 + ((k8 * 16) ^ ((co & 7) << 4)));
            cp_async16(bb + so, g_whi + (size_t)co * Ktot + kbase + k8 * 8);
        }
    };

    auto gatherA = [&](int kb, int buf) {
        const int tap = kb >> 2;
        const int c0  = (kb & 3) * 64;
        ushort4 id = tbl_idx[gpx * 9 + tap];
        float4  wt = tbl_w[gpx * 9 + tap];
        const size_t cbase = ((size_t)b * 4096) * 256 + c0 + cg * 16;
        const __half* p0 = g_xhi + cbase + (size_t)id.x * 256;
        const __half* p1 = g_xhi + cbase + (size_t)id.y * 256;
        const __half* p2 = g_xhi + cbase + (size_t)id.z * 256;
        const __half* p3 = g_xhi + cbase + (size_t)id.w * 256;
        const uint32_t ab = (uint32_t)(DF_A0 + buf * DF_ASTR) + grow;
#pragma unroll
        for (int u = 0; u < 2; u++) {
            float v[8];
#pragma unroll
            for (int i = 0; i < 8; i++) v[i] = 0.f;
            accum8s(v, ((const uint4*)p0)[u], wt.x);
            accum8s(v, ((const uint4*)p1)[u], wt.y);
            accum8s(v, ((const uint4*)p2)[u], wt.z);
            accum8s(v, ((const uint4*)p3)[u], wt.w);
            uint4 H;
            H.x = pack_h2(v[0], v[1]);
            H.y = pack_h2(v[2], v[3]);
            H.z = pack_h2(v[4], v[5]);
            H.w = pack_h2(v[6], v[7]);
            uint32_t o = (uint32_t)((cg * 32 + u * 16) ^ pxor);
            *(uint4*)(smem + ab + o) = H;
        }
    };

    float d[4][4][4];
#pragma unroll
    for (int mt = 0; mt < 4; mt++)
#pragma unroll
        for (int nt = 0; nt < 4; nt++)
#pragma unroll
            for (int j = 0; j < 4; j++) d[mt][nt][j] = 0.f;

    stageB(0, 0);
    CP_COMMIT();
    gatherA(0, 0);
    CP_WAIT0();
    __syncthreads();

#pragma unroll 1
    for (int kb = 0; kb < 36; kb++) {
        if (kb < 35) {
            stageB(kb + 1, (kb + 1) & 1);
            CP_COMMIT();
            gatherA(kb + 1, (kb + 1) & 1);
        }

        const uint32_t aA = aBase + (uint32_t)((kb & 1) * DF_ASTR);
        const uint32_t bH = bBase + (uint32_t)((kb & 1) * DF_BSTR);
#pragma unroll
        for (int ks = 0; ks < 4; ks++) {
            const uint32_t acol = (uint32_t)((ks * 32 + asel) ^ lxor);
            const uint32_t bcol = (uint32_t)((ks * 32 + bsel) ^ lxor);
            uint32_t Af[4][4], Bf[2][4];
#pragma unroll
            for (int mt = 0; mt < 4; mt++)
                ldsm4(aA + mt * 2048 + acol, Af[mt]);
            ldsm4(bH + bcol, Bf[0]);
            ldsm4(bH + 2048 + bcol, Bf[1]);
#pragma unroll
            for (int mt = 0; mt < 4; mt++)
#pragma unroll
                for (int nt = 0; nt < 4; nt++) {
                    const uint32_t* bp = &Bf[nt >> 1][(nt & 1) * 2];
                    mma16816h(d[mt][nt], Af[mt], bp);
                }
        }

        if (kb < 35) CP_WAIT0();
        __syncthreads();
    }

    // --- epilogue ---
    {
        const int g   = lane >> 2;
        const int tig = lane & 3;
        float* outb = out + (size_t)b * C2n * HWn + sb;
#pragma unroll
        for (int mt = 0; mt < 4; mt++) {
            const int px0 = wm * 64 + mt * 16 + g;
#pragma unroll
            for (int nt = 0; nt < 4; nt++) {
                const int co0 = wn * 32 + nt * 8 + tig * 2;
                outb[(size_t)co0 * HWn + px0]           = d[mt][nt][0];
                outb[(size_t)(co0 + 1) * HWn + px0]     = d[mt][nt][1];
                outb[(size_t)co0 * HWn + px0 + 8]       = d[mt][nt][2];
                outb[(size_t)(co0 + 1) * HWn + px0 + 8] = d[mt][nt][3];
            }
        }
    }
}

// ----------------------------------------------------------------------------
extern "C" void kernel_launch(void* const* d_in, const int* in_sizes, int n_in,
                              void* d_out, int out_size)
{
    const float* x        = (const float*)d_in[0];
    const float* offset_w = (const float*)d_in[1];
    const float* offset_b = (const float*)d_in[2];
    const float* mod_w    = (const float*)d_in[3];
    const float* mod_b    = (const float*)d_in[4];
    const float* reg_w    = (const float*)d_in[5];
    float* out = (float*)d_out;

    cudaFuncSetAttribute(dfconv_mma_kernel,
                         cudaFuncAttributeMaxDynamicSharedMemorySize, SMEM_BYTES);
    cudaFuncSetAttribute(offmask_mma_kernel,
                         cudaFuncAttributeMaxDynamicSharedMemorySize, OM_SMEM);
    cudaFuncSetAttribute(prep_all_kernel,
                         cudaFuncAttributeMaxDynamicSharedMemorySize, 128 * 65 * 4);

    prep_all_kernel<<<1060, 256, 128 * 65 * 4>>>(x, offset_w, mod_w);
    offmask_mma_kernel<<<348, 256, OM_SMEM>>>(offset_b, mod_b, reg_w);
    dfconv_mma_kernel<<<256, 512, SMEM_BYTES>>>(out);
}